// round 3
// baseline (speedup 1.0000x reference)
#include <cuda_runtime.h>

#define CC 32
#define DD 48
#define HH 64
#define WW 208
#define HW 13312            // HH*WW
#define NELEM (CC*DD*HH*WW) // 20447232
#define CEPS 1e-5f
#define NEGINF -3.402823e38f

typedef unsigned long long ull;

// ---------- scratch (device globals: allocation-free) ----------
__device__ float g_kn[4 * 5 * HW];       // normalized guidance, [dir][j][h][w]
__device__ float g_xt[NELEM];            // x transposed [d][h][w][c]; later reused as act [d][h][c][w]
__device__ float g_accA[NELEM];          // W-scan fwd
__device__ float g_accB[NELEM];          // W-scan bwd
__device__ float g_accC[NELEM];          // H-scan fwd
__device__ float g_accD[NELEM];          // H-scan bwd
__device__ float g_wdup[27 * 32 * 32 * 2]; // weights [tap][ic][oc] dup pairs, bn2-scaled
__device__ float g_bias2[32];
__device__ float g_s1v[32];
__device__ float g_b1v[32];

// ---------- packed f32x2 helpers (Blackwell FFMA2) ----------
__device__ __forceinline__ ull pk2(float lo, float hi) {
    ull r;
    asm("mov.b64 %0, {%1, %2};" : "=l"(r) : "f"(lo), "f"(hi));
    return r;
}
__device__ __forceinline__ ull ffma2(ull a, ull b, ull c) {
    ull d;
    asm("fma.rn.f32x2 %0, %1, %2, %3;" : "=l"(d) : "l"(a), "l"(b), "l"(c));
    return d;
}
__device__ __forceinline__ float2 upk2(ull v) {
    float lo, hi;
    asm("mov.b64 {%0, %1}, %2;" : "=f"(lo), "=f"(hi) : "l"(v));
    return make_float2(lo, hi);
}

// ---------- 1) guidance L1 normalization ----------
__global__ void k_norm(const float* __restrict__ g) {
    int i = blockIdx.x * blockDim.x + threadIdx.x;
    if (i >= 4 * HW) return;
    int dir = i / HW;
    int hw  = i % HW;
    float v[5];
    float s = 0.f;
#pragma unroll
    for (int j = 0; j < 5; j++) {
        v[j] = g[(5 * dir + j) * HW + hw];
        s += fabsf(v[j]);
    }
    float inv = 1.f / fmaxf(s, 1e-12f);
#pragma unroll
    for (int j = 0; j < 5; j++)
        g_kn[(dir * 5 + j) * HW + hw] = v[j] * inv;
}

// ---------- 2) transpose NCDHW -> [d][h][w][c] ----------
__global__ void k_transpose(const float* __restrict__ x) {
    __shared__ float t[32][209];
    int d = blockIdx.x / HH;
    int h = blockIdx.x % HH;
    for (int i = threadIdx.x; i < 32 * WW; i += blockDim.x) {
        int c = i / WW, w = i % WW;
        t[c][w] = x[((c * DD + d) * HH + h) * WW + w];
    }
    __syncthreads();
    float* dst = g_xt + (d * HH + h) * WW * 32;
    for (int i = threadIdx.x; i < WW * 32; i += blockDim.x) {
        dst[i] = t[i & 31][i >> 5];
    }
}

// ---------- 3) weight prep ----------
__global__ void k_prep(const float* __restrict__ cw,
                       const float* __restrict__ g1, const float* __restrict__ b1,
                       const float* __restrict__ m1, const float* __restrict__ v1,
                       const float* __restrict__ g2, const float* __restrict__ b2,
                       const float* __restrict__ m2, const float* __restrict__ v2) {
    int i = blockIdx.x * blockDim.x + threadIdx.x;
    if (i < 27 * 1024) {
        int tap = i >> 10;
        int r   = i & 1023;
        int ic  = r >> 5;
        int oc  = r & 31;
        float s2 = g2[oc] * rsqrtf(v2[oc] + CEPS);
        float wv = cw[(oc * 32 + ic) * 27 + tap] * s2;
        g_wdup[i * 2 + 0] = wv;
        g_wdup[i * 2 + 1] = wv;
    }
    if (i < 32) {
        float s2 = g2[i] * rsqrtf(v2[i] + CEPS);
        g_bias2[i] = b2[i] - m2[i] * s2;
        float s1 = g1[i] * rsqrtf(v1[i] + CEPS);
        g_s1v[i] = s1;
        g_b1v[i] = b1[i] - m1[i] * s1;
    }
}

// ---------- 4) fused 4-direction scan kernel ----------
// blocks [0,512): W-scans (h=bx&63, dir=(bx>>6)&1, cg=bx>>7), 208 steps.
// blocks [512,2176): H-scans (i=bx-512: w=i%208, r=i/208, dir=r&1, cg=r>>1), 64 steps.
// warp = 4 D-slices x 8 channels; 1-step prefetch of x and guidance weights.
__global__ void __launch_bounds__(32) k_scan() {
    int lane = threadIdx.x;
    int ds = lane >> 3;
    int cl = lane & 7;
    int bx = blockIdx.x;

    int nsteps, pitch, p0;           // pitch: element stride between steps in (h,w) plane
    const float* kb; float* ob; int kpitch;
    int cg;
    int planeIdx0;                   // hw-plane index of first step
    if (bx < 512) {
        int h = bx & 63;
        int dir = (bx >> 6) & 1;
        cg = bx >> 7;
        nsteps = WW;
        kb = g_kn + dir * 5 * HW + h * WW;
        ob = dir ? g_accB : g_accA;
        int ps = dir ? -1 : 1;
        p0 = dir ? (WW - 1) : 0;
        pitch = ps;
        kpitch = ps;
        planeIdx0 = h * WW + p0;
    } else {
        int i = bx - 512;
        int w = i % 208;
        int r = i / 208;
        int dir = r & 1;
        cg = r >> 1;
        nsteps = HH;
        kb = g_kn + (2 + dir) * 5 * HW + w;
        ob = dir ? g_accD : g_accC;
        int hs = dir ? -1 : 1;
        int h0 = dir ? (HH - 1) : 0;
        pitch = hs * WW;
        kpitch = hs * WW;
        planeIdx0 = h0 * WW + w;
        p0 = h0 * WW;                // kb index base (kb already offset by w)
    }
    int c = cg * 8 + cl;
    int d0 = ds * 12;

    const float* xp = g_xt + ((long long)d0 * HW + planeIdx0) * 32 + c;
    float* op = ob + ((long long)d0 * HW + planeIdx0) * 32 + c;
    const long long DSTR = (long long)HW * 32;
    const long long PSTR = (long long)pitch * 32;
    const float* kp = (bx < 512) ? (kb + (p0 & (WW - 1)) ) : (kb + p0);
    // unified kb pointer at first step:
    if (bx < 512) kp = kb + ( (pitch > 0) ? 0 : (WW - 1) );

    float A[12], xv[12], wv[5];
    float lmx = NEGINF;
#pragma unroll
    for (int j = 0; j < 12; j++) {
        xv[j] = xp[j * DSTR];
        A[j] = xv[j];
        lmx = fmaxf(lmx, A[j]);
    }
#pragma unroll
    for (int j = 0; j < 5; j++) wv[j] = kp[j * HW];
    float gmx = fmaxf(lmx, __shfl_xor_sync(0xffffffffu, lmx, 8));
    gmx = fmaxf(gmx, __shfl_xor_sync(0xffffffffu, gmx, 16));

    for (int s = 0; s < nsteps; s++) {
        bool last = (s == nsteps - 1);
        const float* xpn = last ? xp : (xp + PSTR);
        const float* kpn = last ? kp : (kp + kpitch);
        float xn[12], wn[5];
#pragma unroll
        for (int j = 0; j < 12; j++) xn[j] = xpn[j * DSTR];
#pragma unroll
        for (int j = 0; j < 5; j++) wn[j] = kpn[j * HW];

        float fromUp = __shfl_up_sync(0xffffffffu, A[11], 8);
        float fromDn = __shfl_down_sync(0xffffffffu, A[0], 8);
        float up0   = (ds == 0) ? A[0]  : fromUp;
        float dnTop = (ds == 3) ? A[11] : fromDn;
        float w0 = wv[0], w1 = wv[1], w2 = wv[2], w3 = wv[3], w4 = wv[4];
        float prevOld = A[0];
#pragma unroll
        for (int j = 0; j < 12; j++) {
            float old = A[j];
            float up = (j == 0) ? up0 : prevOld;
            float dn = (j == 11) ? dnTop : A[j + 1];
            float nv = w0 * xv[j] + w1 * old + w2 * up + w3 * dn + w4 * gmx;
            op[j * DSTR] = nv;
            A[j] = nv;
            prevOld = old;
        }
        // tree max over 12
        float t0 = fmaxf(A[0], A[1]),  t1 = fmaxf(A[2], A[3]);
        float t2 = fmaxf(A[4], A[5]),  t3 = fmaxf(A[6], A[7]);
        float t4 = fmaxf(A[8], A[9]),  t5 = fmaxf(A[10], A[11]);
        float u0 = fmaxf(t0, t1), u1 = fmaxf(t2, t3), u2 = fmaxf(t4, t5);
        float lm = fmaxf(u0, fmaxf(u1, u2));
        lm = fmaxf(lm, __shfl_xor_sync(0xffffffffu, lm, 8));
        gmx = fmaxf(lm, __shfl_xor_sync(0xffffffffu, lm, 16));

#pragma unroll
        for (int j = 0; j < 12; j++) xv[j] = xn[j];
#pragma unroll
        for (int j = 0; j < 5; j++) wv[j] = wn[j];
        xp = xpn;
        kp = kpn;
        op += PSTR;
    }
}

// ---------- 5) combine: relu(bn1(max of 4 dirs))) + transpose [w][c] -> [c][w] into g_xt ----------
__global__ void __launch_bounds__(256) k_combine() {
    __shared__ float t_sm[32][212];
    __shared__ float s1s[32], b1s[32];
    int tid = threadIdx.x;
    int d = blockIdx.x / HH;
    int h = blockIdx.x % HH;
    if (tid < 32) { s1s[tid] = g_s1v[tid]; b1s[tid] = g_b1v[tid]; }
    __syncthreads();
    long long rb = (long long)(d * HH + h) * (WW * 32);
    const float4* pa = (const float4*)(g_accA + rb);
    const float4* pb = (const float4*)(g_accB + rb);
    const float4* pc = (const float4*)(g_accC + rb);
    const float4* pd = (const float4*)(g_accD + rb);
    for (int i = tid; i < (WW * 32) / 4; i += 256) {
        float4 a = pa[i];
        float4 b = pb[i];
        float4 cc = pc[i];
        float4 dd = pd[i];
        int c = (i * 4) & 31;
        int w = (i * 4) >> 5;
        float vx = fmaxf(fmaxf(a.x, b.x), fmaxf(cc.x, dd.x));
        float vy = fmaxf(fmaxf(a.y, b.y), fmaxf(cc.y, dd.y));
        float vz = fmaxf(fmaxf(a.z, b.z), fmaxf(cc.z, dd.z));
        float vw = fmaxf(fmaxf(a.w, b.w), fmaxf(cc.w, dd.w));
        t_sm[c + 0][w] = fmaxf(vx * s1s[c + 0] + b1s[c + 0], 0.f);
        t_sm[c + 1][w] = fmaxf(vy * s1s[c + 1] + b1s[c + 1], 0.f);
        t_sm[c + 2][w] = fmaxf(vz * s1s[c + 2] + b1s[c + 2], 0.f);
        t_sm[c + 3][w] = fmaxf(vw * s1s[c + 3] + b1s[c + 3], 0.f);
    }
    __syncthreads();
    float* dst = g_xt + rb;
    for (int i = tid; i < 32 * 52; i += 256) {
        int c = i / 52, b = i % 52;
        float4 v = *(const float4*)&t_sm[c][4 * b];
        *(float4*)&dst[c * WW + 4 * b] = v;
    }
}

// ---------- 6) conv3d 3x3x3 (input pre-activated) + BN2 + residual + ReLU ----------
// block = one (d,h); 128 threads = 4 oc-quads x 32 wg lanes (26 active).
// a_sm rows front-padded: [pad4 | 208 | pad4], aligned STS.128 staging.
#define ASTR 216
__global__ void __launch_bounds__(128) k_conv(const float* __restrict__ xres,
                                              float* __restrict__ out) {
    __shared__ float a_sm[32 * ASTR];
    __shared__ float w_sm[3 * 1024 * 2];
    __shared__ float bias2s[32];

    int tid = threadIdx.x;
    int h = blockIdx.x;
    int d = blockIdx.y;
    int ocq = tid >> 5;
    int wg  = tid & 31;

    if (tid < 32) bias2s[tid] = g_bias2[tid];
    for (int i = tid; i < 32 * ASTR; i += 128) a_sm[i] = 0.f;

    ull acc[8][4];
#pragma unroll
    for (int o = 0; o < 8; o++)
#pragma unroll
        for (int t = 0; t < 4; t++) acc[o][t] = 0ull;

    int base = 4 + 8 * wg;

#pragma unroll
    for (int kd = 0; kd < 3; kd++) {
        int din = d + kd - 1;
        if ((unsigned)din >= DD) continue;
#pragma unroll
        for (int kh = 0; kh < 3; kh++) {
            int hin = h + kh - 1;
            if ((unsigned)hin >= HH) continue;
            __syncthreads();
            // stage activations: plain aligned copies
            const float* src = g_xt + (long long)(din * HH + hin) * (WW * 32);
            for (int i = tid; i < 32 * 52; i += 128) {
                int ic = i / 52, b = i % 52;
                float4 v = *(const float4*)&src[ic * WW + 4 * b];
                *(float4*)&a_sm[ic * ASTR + 4 + 4 * b] = v;
            }
            // stage dup weights for 3 kw taps (6144 floats)
            const float4* wsrc = (const float4*)(g_wdup + (kd * 9 + kh * 3) * 2048);
            for (int i = tid; i < 1536; i += 128)
                ((float4*)w_sm)[i] = wsrc[i];
            __syncthreads();

            if (wg < 26) {
#pragma unroll 4
                for (int ic = 0; ic < 32; ic++) {
                    const float* ar = a_sm + ic * ASTR;
                    float4 a0 = *(const float4*)(ar + base);
                    float4 a1 = *(const float4*)(ar + base + 4);
                    float m1 = ar[base - 1];
                    float p8 = ar[base + 8];
                    ull E0 = pk2(a0.x, a0.y), E1 = pk2(a0.z, a0.w);
                    ull E2 = pk2(a1.x, a1.y), E3 = pk2(a1.z, a1.w);
                    ull M  = pk2(m1, a0.x);
                    ull O1 = pk2(a0.y, a0.z), O2 = pk2(a0.w, a1.x);
                    ull O3 = pk2(a1.y, a1.z);
                    ull P  = pk2(a1.w, p8);
                    const ull* wrow = (const ull*)(w_sm) + ic * 32 + 8 * ocq;
#pragma unroll
                    for (int kw = 0; kw < 3; kw++) {
                        ull Ap0 = (kw == 0) ? M  : (kw == 1) ? E0 : O1;
                        ull Ap1 = (kw == 0) ? O1 : (kw == 1) ? E1 : O2;
                        ull Ap2 = (kw == 0) ? O2 : (kw == 1) ? E2 : O3;
                        ull Ap3 = (kw == 0) ? O3 : (kw == 1) ? E3 : P;
                        const ulonglong2* wp = (const ulonglong2*)(wrow + kw * 1024);
                        ulonglong2 wab = wp[0];
                        ulonglong2 wcd = wp[1];
                        ulonglong2 wef = wp[2];
                        ulonglong2 wgh = wp[3];
                        ull W[8] = {wab.x, wab.y, wcd.x, wcd.y,
                                    wef.x, wef.y, wgh.x, wgh.y};
#pragma unroll
                        for (int o = 0; o < 8; o++) {
                            acc[o][0] = ffma2(W[o], Ap0, acc[o][0]);
                            acc[o][1] = ffma2(W[o], Ap1, acc[o][1]);
                            acc[o][2] = ffma2(W[o], Ap2, acc[o][2]);
                            acc[o][3] = ffma2(W[o], Ap3, acc[o][3]);
                        }
                    }
                }
            }
        }
    }

    if (wg < 26) {
#pragma unroll
        for (int o = 0; o < 8; o++) {
            int oc = 8 * ocq + o;
            int ob = ((oc * DD + d) * HH + h) * WW + 8 * wg;
            float bi = bias2s[oc];
#pragma unroll
            for (int t = 0; t < 4; t++) {
                float2 f = upk2(acc[o][t]);
                float2 r = *(const float2*)&xres[ob + 2 * t];
                float o0 = fmaxf(f.x + bi + r.x, 0.f);
                float o1 = fmaxf(f.y + bi + r.y, 0.f);
                *(float2*)&out[ob + 2 * t] = make_float2(o0, o1);
            }
        }
    }
}

// ---------- launcher ----------
extern "C" void kernel_launch(void* const* d_in, const int* in_sizes, int n_in,
                              void* d_out, int out_size) {
    const float* x  = (const float*)d_in[0];
    const float* g  = (const float*)d_in[1];
    const float* cw = (const float*)d_in[2];
    const float* g1 = (const float*)d_in[3];
    const float* b1 = (const float*)d_in[4];
    const float* m1 = (const float*)d_in[5];
    const float* v1 = (const float*)d_in[6];
    const float* g2 = (const float*)d_in[7];
    const float* b2 = (const float*)d_in[8];
    const float* m2 = (const float*)d_in[9];
    const float* v2 = (const float*)d_in[10];
    float* out = (float*)d_out;

    k_norm<<<(4 * HW + 255) / 256, 256>>>(g);
    k_prep<<<(27 * 1024 + 255) / 256, 256>>>(cw, g1, b1, m1, v1, g2, b2, m2, v2);
    k_transpose<<<DD * HH, 256>>>(x);
    k_scan<<<2176, 32>>>();
    k_combine<<<DD * HH, 256>>>();
    k_conv<<<dim3(HH, DD), 128>>>(x, out);
}

// round 6
// speedup vs baseline: 1.8952x; 1.8952x over previous
#include <cuda_runtime.h>
#include <cuda_bf16.h>
#include <cstdint>
#include <cstring>

#define CC 32
#define DD 48
#define HH 64
#define WW 208
#define HW 13312            // HH*WW
#define NELEM (CC*DD*HH*WW) // 20447232
#define CEPS 1e-5f
#define NEGINF -3.402823e38f

typedef unsigned long long ull;

// ---------- scratch (device globals: allocation-free) ----------
__device__ float g_kn[4 * 5 * HW];        // normalized guidance
__device__ float g_xt[NELEM];             // x transposed [d][h][w][c]
__device__ float g_accA[NELEM];           // W fwd
__device__ float g_accB[NELEM];           // W bwd
__device__ float g_accC[NELEM];           // H fwd
__device__ float g_accD[NELEM];           // H bwd
__device__ __nv_bfloat16 g_bh[NELEM];     // activation hi split [d][h][w][c]
__device__ __nv_bfloat16 g_bl[NELEM];     // activation lo split
__device__ uint32_t g_wfrag[2 * 27 * 512]; // B fragments [sp][tap][kt][nt][lane][reg]
__device__ float g_bias2[32];
__device__ float g_s1v[32];
__device__ float g_b1v[32];

// ---------- helpers ----------
__device__ __forceinline__ uint32_t smem_u32(const void* p) {
    uint32_t a;
    asm("{ .reg .u64 t; cvta.to.shared.u64 t, %1; cvt.u32.u64 %0, t; }" : "=r"(a) : "l"(p));
    return a;
}
__device__ __forceinline__ void ldm4(uint32_t* r, uint32_t addr) {
    asm volatile("ldmatrix.sync.aligned.m8n8.x4.shared.b16 {%0,%1,%2,%3}, [%4];"
                 : "=r"(r[0]), "=r"(r[1]), "=r"(r[2]), "=r"(r[3]) : "r"(addr));
}
__device__ __forceinline__ void mma16816(float* c, const uint32_t* a, uint32_t b0, uint32_t b1) {
    asm volatile("mma.sync.aligned.m16n8k16.row.col.f32.bf16.bf16.f32 "
                 "{%0,%1,%2,%3}, {%4,%5,%6,%7}, {%8,%9}, {%0,%1,%2,%3};"
                 : "+f"(c[0]), "+f"(c[1]), "+f"(c[2]), "+f"(c[3])
                 : "r"(a[0]), "r"(a[1]), "r"(a[2]), "r"(a[3]), "r"(b0), "r"(b1));
}
__device__ __forceinline__ unsigned short bf16bits(__nv_bfloat16 v) {
    unsigned short s;
    memcpy(&s, &v, 2);
    return s;
}

// ---------- 1) guidance L1 normalization ----------
__global__ void k_norm(const float* __restrict__ g) {
    int i = blockIdx.x * blockDim.x + threadIdx.x;
    if (i >= 4 * HW) return;
    int dir = i / HW;
    int hw  = i % HW;
    float v[5];
    float s = 0.f;
#pragma unroll
    for (int j = 0; j < 5; j++) {
        v[j] = g[(5 * dir + j) * HW + hw];
        s += fabsf(v[j]);
    }
    float inv = 1.f / fmaxf(s, 1e-12f);
#pragma unroll
    for (int j = 0; j < 5; j++)
        g_kn[(dir * 5 + j) * HW + hw] = v[j] * inv;
}

// ---------- 2) transpose NCDHW -> [d][h][w][c] ----------
__global__ void k_transpose(const float* __restrict__ x) {
    __shared__ float t[32][209];
    int d = blockIdx.x / HH;
    int h = blockIdx.x % HH;
    for (int i = threadIdx.x; i < 32 * WW; i += blockDim.x) {
        int c = i / WW, w = i % WW;
        t[c][w] = x[((c * DD + d) * HH + h) * WW + w];
    }
    __syncthreads();
    float* dst = g_xt + (d * HH + h) * WW * 32;
    for (int i = threadIdx.x; i < WW * 32; i += blockDim.x) {
        dst[i] = t[i & 31][i >> 5];
    }
}

// ---------- 3) prep: BN params + bf16-split B fragments in mma frag order ----------
// frag layout: offset = (sp*27+tap)*512 + ((kt*4+nt)*32+lane)*2 + reg  (uint32 = 2 bf16)
// value(e) = wscaled[oc = nt*8 + lane/4][ic = kt*16 + (lane%4)*2 + reg*8 + e]
__global__ void k_wfrag(const float* __restrict__ cw,
                        const float* __restrict__ g1, const float* __restrict__ b1,
                        const float* __restrict__ m1, const float* __restrict__ v1,
                        const float* __restrict__ g2, const float* __restrict__ b2,
                        const float* __restrict__ m2, const float* __restrict__ v2) {
    int i = blockIdx.x * blockDim.x + threadIdx.x;
    if (i < 2 * 27 * 512) {
        int reg  = i & 1;
        int lane = (i >> 1) & 31;
        int nt   = (i >> 6) & 3;
        int kt   = (i >> 8) & 1;
        int rest = i >> 9;
        int tap  = rest % 27;
        int sp   = rest / 27;
        int oc   = nt * 8 + (lane >> 2);
        int icb  = kt * 16 + (lane & 3) * 2 + reg * 8;
        float s2 = g2[oc] * rsqrtf(v2[oc] + CEPS);
        uint32_t pack = 0;
#pragma unroll
        for (int e = 0; e < 2; e++) {
            int ic = icb + e;
            float wv = cw[(oc * 32 + ic) * 27 + tap] * s2;
            __nv_bfloat16 wh = __float2bfloat16(wv);
            __nv_bfloat16 val = sp ? __float2bfloat16(wv - __bfloat162float(wh)) : wh;
            pack |= (uint32_t)bf16bits(val) << (16 * e);
        }
        g_wfrag[i] = pack;
    }
    if (i < 32) {
        float s2 = g2[i] * rsqrtf(v2[i] + CEPS);
        g_bias2[i] = b2[i] - m2[i] * s2;
        float s1 = g1[i] * rsqrtf(v1[i] + CEPS);
        g_s1v[i] = s1;
        g_b1v[i] = b1[i] - m1[i] * s1;
    }
}

// ---------- 4) fused 4-direction scan ----------
__global__ void __launch_bounds__(32) k_scan() {
    int lane = threadIdx.x;
    int ds = lane >> 3;
    int cl = lane & 7;
    int bx = blockIdx.x;

    int nsteps, pitch, p0;
    const float* kb; float* ob; int kpitch;
    int cg;
    int planeIdx0;
    if (bx < 512) {
        int h = bx & 63;
        int dir = (bx >> 6) & 1;
        cg = bx >> 7;
        nsteps = WW;
        kb = g_kn + dir * 5 * HW + h * WW;
        ob = dir ? g_accB : g_accA;
        int ps = dir ? -1 : 1;
        p0 = dir ? (WW - 1) : 0;
        pitch = ps;
        kpitch = ps;
        planeIdx0 = h * WW + p0;
    } else {
        int i = bx - 512;
        int w = i % 208;
        int r = i / 208;
        int dir = r & 1;
        cg = r >> 1;
        nsteps = HH;
        kb = g_kn + (2 + dir) * 5 * HW + w;
        ob = dir ? g_accD : g_accC;
        int hs = dir ? -1 : 1;
        int h0 = dir ? (HH - 1) : 0;
        pitch = hs * WW;
        kpitch = hs * WW;
        planeIdx0 = h0 * WW + w;
        p0 = h0 * WW;
    }
    int c = cg * 8 + cl;
    int d0 = ds * 12;

    const float* xp = g_xt + ((long long)d0 * HW + planeIdx0) * 32 + c;
    float* op = ob + ((long long)d0 * HW + planeIdx0) * 32 + c;
    const long long DSTR = (long long)HW * 32;
    const long long PSTR = (long long)pitch * 32;
    const float* kp;
    if (bx < 512) kp = kb + ((pitch > 0) ? 0 : (WW - 1));
    else kp = kb + p0;

    float A[12], xv[12], wv[5];
    float lmx = NEGINF;
#pragma unroll
    for (int j = 0; j < 12; j++) {
        xv[j] = xp[j * DSTR];
        A[j] = xv[j];
        lmx = fmaxf(lmx, A[j]);
    }
#pragma unroll
    for (int j = 0; j < 5; j++) wv[j] = kp[j * HW];
    float gmx = fmaxf(lmx, __shfl_xor_sync(0xffffffffu, lmx, 8));
    gmx = fmaxf(gmx, __shfl_xor_sync(0xffffffffu, gmx, 16));

    for (int s = 0; s < nsteps; s++) {
        bool last = (s == nsteps - 1);
        const float* xpn = last ? xp : (xp + PSTR);
        const float* kpn = last ? kp : (kp + kpitch);
        float xn[12], wn[5];
#pragma unroll
        for (int j = 0; j < 12; j++) xn[j] = xpn[j * DSTR];
#pragma unroll
        for (int j = 0; j < 5; j++) wn[j] = kpn[j * HW];

        float fromUp = __shfl_up_sync(0xffffffffu, A[11], 8);
        float fromDn = __shfl_down_sync(0xffffffffu, A[0], 8);
        float up0   = (ds == 0) ? A[0]  : fromUp;
        float dnTop = (ds == 3) ? A[11] : fromDn;
        float w0 = wv[0], w1 = wv[1], w2 = wv[2], w3 = wv[3], w4 = wv[4];
        float prevOld = A[0];
#pragma unroll
        for (int j = 0; j < 12; j++) {
            float old = A[j];
            float up = (j == 0) ? up0 : prevOld;
            float dn = (j == 11) ? dnTop : A[j + 1];
            float nv = w0 * xv[j] + w1 * old + w2 * up + w3 * dn + w4 * gmx;
            op[j * DSTR] = nv;
            A[j] = nv;
            prevOld = old;
        }
        float t0 = fmaxf(A[0], A[1]),  t1 = fmaxf(A[2], A[3]);
        float t2 = fmaxf(A[4], A[5]),  t3 = fmaxf(A[6], A[7]);
        float t4 = fmaxf(A[8], A[9]),  t5 = fmaxf(A[10], A[11]);
        float u0 = fmaxf(t0, t1), u1 = fmaxf(t2, t3), u2 = fmaxf(t4, t5);
        float lm = fmaxf(u0, fmaxf(u1, u2));
        lm = fmaxf(lm, __shfl_xor_sync(0xffffffffu, lm, 8));
        gmx = fmaxf(lm, __shfl_xor_sync(0xffffffffu, lm, 16));

#pragma unroll
        for (int j = 0; j < 12; j++) xv[j] = xn[j];
#pragma unroll
        for (int j = 0; j < 5; j++) wv[j] = wn[j];
        xp = xpn;
        kp = kpn;
        op += PSTR;
    }
}

// ---------- 5) combine: relu(bn1(max4)) -> bf16 hi/lo splits, [d][h][w][c] ----------
__global__ void __launch_bounds__(256) k_combine() {
    __shared__ float s1s[32], b1s[32];
    int tid = threadIdx.x;
    if (tid < 32) { s1s[tid] = g_s1v[tid]; b1s[tid] = g_b1v[tid]; }
    __syncthreads();
    int i = blockIdx.x * 256 + tid;
    if (i >= NELEM / 4) return;
    float4 a = ((const float4*)g_accA)[i];
    float4 b = ((const float4*)g_accB)[i];
    float4 cc = ((const float4*)g_accC)[i];
    float4 dd = ((const float4*)g_accD)[i];
    int c0 = (i * 4) & 31;
    float v[4];
    v[0] = fmaxf(fmaxf(fmaxf(a.x, b.x), fmaxf(cc.x, dd.x)) * s1s[c0 + 0] + b1s[c0 + 0], 0.f);
    v[1] = fmaxf(fmaxf(fmaxf(a.y, b.y), fmaxf(cc.y, dd.y)) * s1s[c0 + 1] + b1s[c0 + 1], 0.f);
    v[2] = fmaxf(fmaxf(fmaxf(a.z, b.z), fmaxf(cc.z, dd.z)) * s1s[c0 + 2] + b1s[c0 + 2], 0.f);
    v[3] = fmaxf(fmaxf(fmaxf(a.w, b.w), fmaxf(cc.w, dd.w)) * s1s[c0 + 3] + b1s[c0 + 3], 0.f);
    __nv_bfloat16 hb[4], lb[4];
#pragma unroll
    for (int j = 0; j < 4; j++) {
        hb[j] = __float2bfloat16(v[j]);
        lb[j] = __float2bfloat16(v[j] - __bfloat162float(hb[j]));
    }
    __nv_bfloat162* ph = (__nv_bfloat162*)g_bh;
    __nv_bfloat162* pl = (__nv_bfloat162*)g_bl;
    __nv_bfloat162 h0; h0.x = hb[0]; h0.y = hb[1];
    __nv_bfloat162 h1; h1.x = hb[2]; h1.y = hb[3];
    __nv_bfloat162 l0; l0.x = lb[0]; l0.y = lb[1];
    __nv_bfloat162 l1; l1.x = lb[2]; l1.y = lb[3];
    ph[2 * i] = h0; ph[2 * i + 1] = h1;
    pl[2 * i] = l0; pl[2 * i + 1] = l1;
}

// ---------- 6) conv via warp HMMA (m16n8k16 bf16): 27 shifted GEMMs, 2-term split ----------
// CTA = M=128 w-rows (valid 104) x N=32 oc; 4 warps each m32 x n32.
#define SACT_BYTES (2 * 130 * 32 * 2)   // 16640
#define SW_BYTES   (6 * 512 * 4)        // 12288
__global__ void __launch_bounds__(128) k_mma(const float* __restrict__ xres,
                                             float* __restrict__ out) {
    __shared__ alignas(16) unsigned char sRaw[SACT_BYTES + SW_BYTES];
    __shared__ float sBias[32];
    __nv_bfloat16* sAct = (__nv_bfloat16*)sRaw;
    uint32_t* sW = (uint32_t*)(sRaw + SACT_BYTES);
    float* sEpi = (float*)sRaw;   // reused after compute

    int tid = threadIdx.x;
    int wid = tid >> 5;
    int lane = tid & 31;
    int h = blockIdx.x;
    int d = blockIdx.y;
    int w0 = blockIdx.z * 104;

    if (tid < 32) sBias[tid] = g_bias2[tid];

    uint32_t sact_u = smem_u32(sAct);
    // ldmatrix per-lane base: row-within-tile + 16B column group
    uint32_t lm_lane = (uint32_t)((lane & 15) * 64 + (lane >> 4) * 16);

    float acc[2][4][4];
#pragma unroll
    for (int mt = 0; mt < 2; mt++)
#pragma unroll
        for (int nt = 0; nt < 4; nt++)
#pragma unroll
            for (int r = 0; r < 4; r++) acc[mt][nt][r] = 0.f;

#pragma unroll
    for (int kd = 0; kd < 3; kd++) {
        int din = d + kd - 1;
        if ((unsigned)din >= DD) continue;
#pragma unroll
        for (int kh = 0; kh < 3; kh++) {
            int hin = h + kh - 1;
            if ((unsigned)hin >= HH) continue;

            __syncthreads();    // previous phase's reads complete
            // stage activations: rows w0-1 .. w0+128 (130) x 32 bf16, hi+lo
            {
                long long rowb = (long long)(din * HH + hin) * WW;
                for (int c = tid; c < 1040; c += 128) {
                    int sp  = c / 520;
                    int rem = c - sp * 520;
                    int r = rem >> 2, q = rem & 3;
                    int w = w0 - 1 + r;
                    uint4 v = make_uint4(0u, 0u, 0u, 0u);
                    if ((unsigned)w < WW) {
                        const __nv_bfloat16* gs = (sp ? g_bl : g_bh) + (rowb + w) * 32 + q * 8;
                        v = *(const uint4*)gs;
                    }
                    *((uint4*)(sAct + (sp * 130 + r) * 32) + q) = v;
                }
            }
            // stage 6 weight-frag slabs (kw x sp), 512 u32 each
            {
                int tap3 = kd * 9 + kh * 3;
                for (int c = tid; c < 768; c += 128) {
                    int slab = c >> 7;          // = kw*2+sp
                    int kw = slab >> 1, sp = slab & 1;
                    const uint4* src = (const uint4*)(g_wfrag + (sp * 27 + tap3 + kw) * 512);
                    ((uint4*)sW)[c] = src[c & 127];
                }
            }
            __syncthreads();

#pragma unroll
            for (int kw = 0; kw < 3; kw++) {
                uint32_t Afr[2][2][2][4];       // [asp][mt][kt][4]
#pragma unroll
                for (int asp = 0; asp < 2; asp++)
#pragma unroll
                    for (int mt = 0; mt < 2; mt++)
#pragma unroll
                        for (int kt = 0; kt < 2; kt++) {
                            uint32_t addr = sact_u + asp * 8320 + lm_lane
                                          + (uint32_t)((wid * 32 + mt * 16 + kw) * 64 + kt * 32);
                            ldm4(Afr[asp][mt][kt], addr);
                        }
                uint2 Bfr[2][2][4];             // [bsp][kt][nt]
#pragma unroll
                for (int bsp = 0; bsp < 2; bsp++)
#pragma unroll
                    for (int kt = 0; kt < 2; kt++)
#pragma unroll
                        for (int nt = 0; nt < 4; nt++)
                            Bfr[bsp][kt][nt] = ((const uint2*)sW)[
                                (kw * 2 + bsp) * 256 + (kt * 4 + nt) * 32 + lane];
#pragma unroll
                for (int cb = 0; cb < 3; cb++) {        // (ah,bh), (ah,bl), (al,bh)
                    int asp = (cb == 2) ? 1 : 0;
                    int bsp = (cb == 1) ? 1 : 0;
#pragma unroll
                    for (int mt = 0; mt < 2; mt++)
#pragma unroll
                        for (int nt = 0; nt < 4; nt++)
#pragma unroll
                            for (int kt = 0; kt < 2; kt++)
                                mma16816(acc[mt][nt], Afr[asp][mt][kt],
                                         Bfr[bsp][kt][nt].x, Bfr[bsp][kt][nt].y);
                }
            }
        }
    }

    __syncthreads();
    // write accumulators to sEpi[m][oc] (stride 33)
#pragma unroll
    for (int mt = 0; mt < 2; mt++)
#pragma unroll
        for (int nt = 0; nt < 4; nt++) {
            int r = wid * 32 + mt * 16 + (lane >> 2);
            int c = nt * 8 + (lane & 3) * 2;
            sEpi[r * 33 + c]           = acc[mt][nt][0];
            sEpi[r * 33 + c + 1]       = acc[mt][nt][1];
            sEpi[(r + 8) * 33 + c]     = acc[mt][nt][2];
            sEpi[(r + 8) * 33 + c + 1] = acc[mt][nt][3];
        }
    __syncthreads();

    if (tid < 104) {
        int w = w0 + tid;
#pragma unroll
        for (int oc = 0; oc < 32; oc++) {
            long long idx = ((long long)(oc * DD + d) * HH + h) * WW + w;
            float val = sEpi[tid * 33 + oc] + sBias[oc] + xres[idx];
            out[idx] = fmaxf(val, 0.f);
        }
    }
}

// ---------- launcher ----------
extern "C" void kernel_launch(void* const* d_in, const int* in_sizes, int n_in,
                              void* d_out, int out_size) {
    const float* x  = (const float*)d_in[0];
    const float* g  = (const float*)d_in[1];
    const float* cw = (const float*)d_in[2];
    const float* g1 = (const float*)d_in[3];
    const float* b1 = (const float*)d_in[4];
    const float* m1 = (const float*)d_in[5];
    const float* v1 = (const float*)d_in[6];
    const float* g2 = (const float*)d_in[7];
    const float* b2 = (const float*)d_in[8];
    const float* m2 = (const float*)d_in[9];
    const float* v2 = (const float*)d_in[10];
    float* out = (float*)d_out;

    k_norm<<<(4 * HW + 255) / 256, 256>>>(g);
    k_wfrag<<<(2 * 27 * 512 + 255) / 256, 256>>>(cw, g1, b1, m1, v1, g2, b2, m2, v2);
    k_transpose<<<DD * HH, 256>>>(x);
    k_scan<<<2176, 32>>>();
    k_combine<<<(NELEM / 4 + 255) / 256, 256>>>();
    k_mma<<<dim3(HH, DD, 2), 128>>>(x, out);
}

// round 8
// speedup vs baseline: 2.3391x; 1.2342x over previous
#include <cuda_runtime.h>
#include <cuda_bf16.h>
#include <cstdint>
#include <cstring>

#define CC 32
#define DD 48
#define HH 64
#define WW 208
#define HW 13312            // HH*WW
#define NELEM (CC*DD*HH*WW) // 20447232
#define CEPS 1e-5f
#define NEGINF -3.402823e38f

typedef unsigned long long ull;

// ---------- scratch (device globals: allocation-free) ----------
__device__ float g_kn[4 * 5 * HW];        // normalized guidance
__device__ float g_xt[NELEM];             // x transposed [d][h][w][c]
__device__ float g_accA[NELEM];           // W fwd
__device__ float g_accB[NELEM];           // W bwd
__device__ float g_accC[NELEM];           // H fwd
__device__ float g_accD[NELEM];           // H bwd
__device__ __nv_bfloat16 g_bh[NELEM];     // activation hi split [d][h][w][c]
__device__ __nv_bfloat16 g_bl[NELEM];     // activation lo split
__device__ uint32_t g_wfrag[2 * 27 * 512]; // B fragments [sp][tap][kt][nt][lane][reg]
__device__ float g_bias2[32];
__device__ float g_s1v[32];
__device__ float g_b1v[32];

// ---------- helpers ----------
__device__ __forceinline__ uint32_t smem_u32(const void* p) {
    uint32_t a;
    asm("{ .reg .u64 t; cvta.to.shared.u64 t, %1; cvt.u32.u64 %0, t; }" : "=r"(a) : "l"(p));
    return a;
}
__device__ __forceinline__ void ldm4(uint32_t* r, uint32_t addr) {
    asm volatile("ldmatrix.sync.aligned.m8n8.x4.shared.b16 {%0,%1,%2,%3}, [%4];"
                 : "=r"(r[0]), "=r"(r[1]), "=r"(r[2]), "=r"(r[3]) : "r"(addr));
}
__device__ __forceinline__ void mma16816(float* c, const uint32_t* a, uint32_t b0, uint32_t b1) {
    asm volatile("mma.sync.aligned.m16n8k16.row.col.f32.bf16.bf16.f32 "
                 "{%0,%1,%2,%3}, {%4,%5,%6,%7}, {%8,%9}, {%0,%1,%2,%3};"
                 : "+f"(c[0]), "+f"(c[1]), "+f"(c[2]), "+f"(c[3])
                 : "r"(a[0]), "r"(a[1]), "r"(a[2]), "r"(a[3]), "r"(b0), "r"(b1));
}
__device__ __forceinline__ unsigned short bf16bits(__nv_bfloat16 v) {
    unsigned short s;
    memcpy(&s, &v, 2);
    return s;
}
__device__ __forceinline__ void cpasync16(uint32_t d, const void* s, bool valid) {
    int sz = valid ? 16 : 0;
    asm volatile("cp.async.cg.shared.global [%0], [%1], 16, %2;"
                 :: "r"(d), "l"(s), "r"(sz) : "memory");
}
__device__ __forceinline__ void cpasync_commit_wait() {
    asm volatile("cp.async.commit_group;" ::: "memory");
    asm volatile("cp.async.wait_group 0;" ::: "memory");
}

// ---------- 1) guidance L1 normalization ----------
__global__ void k_norm(const float* __restrict__ g) {
    int i = blockIdx.x * blockDim.x + threadIdx.x;
    if (i >= 4 * HW) return;
    int dir = i / HW;
    int hw  = i % HW;
    float v[5];
    float s = 0.f;
#pragma unroll
    for (int j = 0; j < 5; j++) {
        v[j] = g[(5 * dir + j) * HW + hw];
        s += fabsf(v[j]);
    }
    float inv = 1.f / fmaxf(s, 1e-12f);
#pragma unroll
    for (int j = 0; j < 5; j++)
        g_kn[(dir * 5 + j) * HW + hw] = v[j] * inv;
}

// ---------- 2) transpose NCDHW -> [d][h][w][c] ----------
__global__ void k_transpose(const float* __restrict__ x) {
    __shared__ float t[32][209];
    int d = blockIdx.x / HH;
    int h = blockIdx.x % HH;
    for (int i = threadIdx.x; i < 32 * WW; i += blockDim.x) {
        int c = i / WW, w = i % WW;
        t[c][w] = x[((c * DD + d) * HH + h) * WW + w];
    }
    __syncthreads();
    float* dst = g_xt + (d * HH + h) * WW * 32;
    for (int i = threadIdx.x; i < WW * 32; i += blockDim.x) {
        dst[i] = t[i & 31][i >> 5];
    }
}

// ---------- 3) prep: BN params + bf16-split B fragments in mma frag order ----------
__global__ void k_wfrag(const float* __restrict__ cw,
                        const float* __restrict__ g1, const float* __restrict__ b1,
                        const float* __restrict__ m1, const float* __restrict__ v1,
                        const float* __restrict__ g2, const float* __restrict__ b2,
                        const float* __restrict__ m2, const float* __restrict__ v2) {
    int i = blockIdx.x * blockDim.x + threadIdx.x;
    if (i < 2 * 27 * 512) {
        int reg  = i & 1;
        int lane = (i >> 1) & 31;
        int nt   = (i >> 6) & 3;
        int kt   = (i >> 8) & 1;
        int rest = i >> 9;
        int tap  = rest % 27;
        int sp   = rest / 27;
        int oc   = nt * 8 + (lane >> 2);
        int icb  = kt * 16 + (lane & 3) * 2 + reg * 8;
        float s2 = g2[oc] * rsqrtf(v2[oc] + CEPS);
        uint32_t pack = 0;
#pragma unroll
        for (int e = 0; e < 2; e++) {
            int ic = icb + e;
            float wv = cw[(oc * 32 + ic) * 27 + tap] * s2;
            __nv_bfloat16 wh = __float2bfloat16(wv);
            __nv_bfloat16 val = sp ? __float2bfloat16(wv - __bfloat162float(wh)) : wh;
            pack |= (uint32_t)bf16bits(val) << (16 * e);
        }
        g_wfrag[i] = pack;
    }
    if (i < 32) {
        float s2 = g2[i] * rsqrtf(v2[i] + CEPS);
        g_bias2[i] = b2[i] - m2[i] * s2;
        float s1 = g1[i] * rsqrtf(v1[i] + CEPS);
        g_s1v[i] = s1;
        g_b1v[i] = b1[i] - m1[i] * s1;
    }
}

// ---------- 4) fused 4-direction scan: warp = 4 D-slices x 8 lanes x float2 (16 ch) ----------
// grid (544, 2): bx<128 -> W-scan (h=bx&63, dir=bx>>6), else H-scan (i=bx-128, w=i%208, dir=i/208)
// by = channel group (16 channels each).
__global__ void __launch_bounds__(32) k_scan() {
    int lane = threadIdx.x;
    int ds = lane >> 3;
    int cl = lane & 7;
    int bx = blockIdx.x;
    int cg = blockIdx.y;

    int nsteps, pitch;
    const float* kb; float* ob; int kpitch;
    int planeIdx0;
    if (bx < 128) {
        int h = bx & 63;
        int dir = bx >> 6;
        nsteps = WW;
        kb = g_kn + dir * 5 * HW + h * WW + (dir ? (WW - 1) : 0);
        ob = dir ? g_accB : g_accA;
        pitch = dir ? -1 : 1;
        kpitch = pitch;
        planeIdx0 = h * WW + (dir ? (WW - 1) : 0);
    } else {
        int i = bx - 128;
        int w = i % 208;
        int dir = i / 208;
        nsteps = HH;
        int h0 = dir ? (HH - 1) : 0;
        kb = g_kn + (2 + dir) * 5 * HW + w + h0 * WW;
        ob = dir ? g_accD : g_accC;
        pitch = (dir ? -1 : 1) * WW;
        kpitch = pitch;
        planeIdx0 = h0 * WW + w;
    }
    int c0 = cg * 16 + cl * 2;
    int d0 = ds * 12;

    const float2* xp = (const float2*)(g_xt + ((long long)d0 * HW + planeIdx0) * 32 + c0);
    float2* op = (float2*)(ob + ((long long)d0 * HW + planeIdx0) * 32 + c0);
    const long long DSTR = (long long)HW * 16;      // float2 units
    const long long PSTR = (long long)pitch * 16;
    const float* kp = kb;

    float2 A[12], xv[12];
    float wv[5];
    float2 lmx = make_float2(NEGINF, NEGINF);
#pragma unroll
    for (int j = 0; j < 12; j++) {
        xv[j] = xp[j * DSTR];
        A[j] = xv[j];
        lmx.x = fmaxf(lmx.x, A[j].x);
        lmx.y = fmaxf(lmx.y, A[j].y);
    }
#pragma unroll
    for (int j = 0; j < 5; j++) wv[j] = kp[j * HW];
    float2 gmx;
    gmx.x = fmaxf(lmx.x, __shfl_xor_sync(0xffffffffu, lmx.x, 8));
    gmx.y = fmaxf(lmx.y, __shfl_xor_sync(0xffffffffu, lmx.y, 8));
    gmx.x = fmaxf(gmx.x, __shfl_xor_sync(0xffffffffu, gmx.x, 16));
    gmx.y = fmaxf(gmx.y, __shfl_xor_sync(0xffffffffu, gmx.y, 16));

    for (int s = 0; s < nsteps; s++) {
        bool last = (s == nsteps - 1);
        const float2* xpn = last ? xp : (xp + PSTR);
        const float* kpn = last ? kp : (kp + kpitch);
        float2 xn[12];
        float wn[5];
#pragma unroll
        for (int j = 0; j < 12; j++) xn[j] = xpn[j * DSTR];
#pragma unroll
        for (int j = 0; j < 5; j++) wn[j] = kpn[j * HW];

        float2 fromUp, fromDn;
        fromUp.x = __shfl_up_sync(0xffffffffu, A[11].x, 8);
        fromUp.y = __shfl_up_sync(0xffffffffu, A[11].y, 8);
        fromDn.x = __shfl_down_sync(0xffffffffu, A[0].x, 8);
        fromDn.y = __shfl_down_sync(0xffffffffu, A[0].y, 8);
        float2 up0   = (ds == 0) ? A[0]  : fromUp;
        float2 dnTop = (ds == 3) ? A[11] : fromDn;
        float w0 = wv[0], w1 = wv[1], w2 = wv[2], w3 = wv[3], w4 = wv[4];
        float2 gterm;
        gterm.x = w4 * gmx.x;
        gterm.y = w4 * gmx.y;
        float2 prevOld = A[0];
#pragma unroll
        for (int j = 0; j < 12; j++) {
            float2 old = A[j];
            float2 up = (j == 0) ? up0 : prevOld;
            float2 dn = (j == 11) ? dnTop : A[j + 1];
            float2 nv;
            nv.x = fmaf(w0, xv[j].x, fmaf(w1, old.x, fmaf(w2, up.x, fmaf(w3, dn.x, gterm.x))));
            nv.y = fmaf(w0, xv[j].y, fmaf(w1, old.y, fmaf(w2, up.y, fmaf(w3, dn.y, gterm.y))));
            op[j * DSTR] = nv;
            A[j] = nv;
            prevOld = old;
        }
        float2 t0, t1, t2, u0;
        t0.x = fmaxf(A[0].x, A[1].x);  t0.y = fmaxf(A[0].y, A[1].y);
        t0.x = fmaxf(t0.x, fmaxf(A[2].x, A[3].x));
        t0.y = fmaxf(t0.y, fmaxf(A[2].y, A[3].y));
        t1.x = fmaxf(fmaxf(A[4].x, A[5].x), fmaxf(A[6].x, A[7].x));
        t1.y = fmaxf(fmaxf(A[4].y, A[5].y), fmaxf(A[6].y, A[7].y));
        t2.x = fmaxf(fmaxf(A[8].x, A[9].x), fmaxf(A[10].x, A[11].x));
        t2.y = fmaxf(fmaxf(A[8].y, A[9].y), fmaxf(A[10].y, A[11].y));
        u0.x = fmaxf(t0.x, fmaxf(t1.x, t2.x));
        u0.y = fmaxf(t0.y, fmaxf(t1.y, t2.y));
        u0.x = fmaxf(u0.x, __shfl_xor_sync(0xffffffffu, u0.x, 8));
        u0.y = fmaxf(u0.y, __shfl_xor_sync(0xffffffffu, u0.y, 8));
        gmx.x = fmaxf(u0.x, __shfl_xor_sync(0xffffffffu, u0.x, 16));
        gmx.y = fmaxf(u0.y, __shfl_xor_sync(0xffffffffu, u0.y, 16));

#pragma unroll
        for (int j = 0; j < 12; j++) xv[j] = xn[j];
#pragma unroll
        for (int j = 0; j < 5; j++) wv[j] = wn[j];
        xp = xpn;
        kp = kpn;
        op += (pitch * 16);
    }
}

// ---------- 5) combine: relu(bn1(max4)) -> bf16 hi/lo splits, [d][h][w][c] ----------
__global__ void __launch_bounds__(256) k_combine() {
    __shared__ float s1s[32], b1s[32];
    int tid = threadIdx.x;
    if (tid < 32) { s1s[tid] = g_s1v[tid]; b1s[tid] = g_b1v[tid]; }
    __syncthreads();
    int i = blockIdx.x * 256 + tid;
    if (i >= NELEM / 4) return;
    float4 a = ((const float4*)g_accA)[i];
    float4 b = ((const float4*)g_accB)[i];
    float4 cc = ((const float4*)g_accC)[i];
    float4 dd = ((const float4*)g_accD)[i];
    int c0 = (i * 4) & 31;
    float v[4];
    v[0] = fmaxf(fmaxf(fmaxf(a.x, b.x), fmaxf(cc.x, dd.x)) * s1s[c0 + 0] + b1s[c0 + 0], 0.f);
    v[1] = fmaxf(fmaxf(fmaxf(a.y, b.y), fmaxf(cc.y, dd.y)) * s1s[c0 + 1] + b1s[c0 + 1], 0.f);
    v[2] = fmaxf(fmaxf(fmaxf(a.z, b.z), fmaxf(cc.z, dd.z)) * s1s[c0 + 2] + b1s[c0 + 2], 0.f);
    v[3] = fmaxf(fmaxf(fmaxf(a.w, b.w), fmaxf(cc.w, dd.w)) * s1s[c0 + 3] + b1s[c0 + 3], 0.f);
    uint32_t hp[2], lp[2];
#pragma unroll
    for (int j = 0; j < 2; j++) {
        __nv_bfloat16 h0 = __float2bfloat16(v[2 * j]);
        __nv_bfloat16 h1 = __float2bfloat16(v[2 * j + 1]);
        __nv_bfloat16 l0 = __float2bfloat16(v[2 * j] - __bfloat162float(h0));
        __nv_bfloat16 l1 = __float2bfloat16(v[2 * j + 1] - __bfloat162float(h1));
        hp[j] = (uint32_t)bf16bits(h0) | ((uint32_t)bf16bits(h1) << 16);
        lp[j] = (uint32_t)bf16bits(l0) | ((uint32_t)bf16bits(l1) << 16);
    }
    ((uint2*)g_bh)[i] = make_uint2(hp[0], hp[1]);
    ((uint2*)g_bl)[i] = make_uint2(lp[0], lp[1]);
}

// ---------- 6) conv via warp HMMA (m16n8k16 bf16): 27 shifted GEMMs, 2-term split ----------
// CTA = M=128 w-rows (valid 104) x N=32 oc; 4 warps each m32 x n32.
// sAct rows padded to 40 bf16 (80B) -> conflict-free ldmatrix.
#define AROW 40
#define ASP_OFF (130 * AROW)            // bf16 elems per split
__global__ void __launch_bounds__(128) k_mma(const float* __restrict__ xres,
                                             float* __restrict__ out) {
    __shared__ alignas(16) __nv_bfloat16 sAct[2 * ASP_OFF];   // 20800 B
    __shared__ alignas(16) uint32_t sW[6 * 512];              // 12288 B
    __shared__ float sBias[32];

    int tid = threadIdx.x;
    int wid = tid >> 5;
    int lane = tid & 31;
    int h = blockIdx.x;
    int d = blockIdx.y;
    int w0 = blockIdx.z * 104;

    if (tid < 32) sBias[tid] = g_bias2[tid];

    uint32_t sact_u = smem_u32(sAct);
    uint32_t sw_u   = smem_u32(sW);
    uint32_t lm_lane = (uint32_t)((lane & 15) * (AROW * 2) + (lane >> 4) * 16);

    float acc[2][4][4];
#pragma unroll
    for (int mt = 0; mt < 2; mt++)
#pragma unroll
        for (int nt = 0; nt < 4; nt++)
#pragma unroll
            for (int r = 0; r < 4; r++) acc[mt][nt][r] = 0.f;

#pragma unroll
    for (int kd = 0; kd < 3; kd++) {
        int din = d + kd - 1;
        if ((unsigned)din >= DD) continue;
#pragma unroll
        for (int kh = 0; kh < 3; kh++) {
            int hin = h + kh - 1;
            if ((unsigned)hin >= HH) continue;

            __syncthreads();    // previous phase's reads complete
            // stage activations via cp.async: rows w0-1..w0+128 (130) x 32 bf16, hi+lo
            {
                long long rowb = (long long)(din * HH + hin) * WW;
                for (int c = tid; c < 1040; c += 128) {
                    int sp  = c / 520;
                    int rem = c - sp * 520;
                    int r = rem >> 2, q = rem & 3;
                    int w = w0 - 1 + r;
                    bool valid = (unsigned)w < WW;
                    int wc = valid ? w : 0;
                    const __nv_bfloat16* gs = (sp ? g_bl : g_bh) + (rowb + wc) * 32 + q * 8;
                    cpasync16(sact_u + (uint32_t)((sp * ASP_OFF + r * AROW) * 2 + q * 16),
                              gs, valid);
                }
            }
            // stage 6 weight-frag slabs (kw x sp), 512 u32 each
            {
                int tap3 = kd * 9 + kh * 3;
                for (int c = tid; c < 768; c += 128) {
                    int slab = c >> 7;
                    int kw = slab >> 1, sp = slab & 1;
                    const uint4* src = (const uint4*)(g_wfrag + (sp * 27 + tap3 + kw) * 512)
                                     + (c & 127);
                    cpasync16(sw_u + (uint32_t)c * 16, src, true);
                }
            }
            cpasync_commit_wait();
            __syncthreads();

#pragma unroll
            for (int kw = 0; kw < 3; kw++) {
                uint32_t Afr[2][2][2][4];       // [asp][mt][kt][4]
#pragma unroll
                for (int asp = 0; asp < 2; asp++)
#pragma unroll
                    for (int mt = 0; mt < 2; mt++)
#pragma unroll
                        for (int kt = 0; kt < 2; kt++) {
                            uint32_t addr = sact_u + (uint32_t)(asp * ASP_OFF * 2) + lm_lane
                                          + (uint32_t)((wid * 32 + mt * 16 + kw) * (AROW * 2)
                                                       + kt * 32);
                            ldm4(Afr[asp][mt][kt], addr);
                        }
                uint2 Bfr[2][2][4];             // [bsp][kt][nt]
#pragma unroll
                for (int bsp = 0; bsp < 2; bsp++)
#pragma unroll
                    for (int kt = 0; kt < 2; kt++)
#pragma unroll
                        for (int nt = 0; nt < 4; nt++)
                            Bfr[bsp][kt][nt] = ((const uint2*)sW)[
                                (kw * 2 + bsp) * 256 + (kt * 4 + nt) * 32 + lane];
#pragma unroll
                for (int cb = 0; cb < 3; cb++) {        // (ah,bh), (ah,bl), (al,bh)
                    int asp = (cb == 2) ? 1 : 0;
                    int bsp = (cb == 1) ? 1 : 0;
#pragma unroll
                    for (int mt = 0; mt < 2; mt++)
#pragma unroll
                        for (int nt = 0; nt < 4; nt++)
#pragma unroll
                            for (int kt = 0; kt < 2; kt++)
                                mma16816(acc[mt][nt], Afr[asp][mt][kt],
                                         Bfr[bsp][kt][nt].x, Bfr[bsp][kt][nt].y);
                }
            }
        }
    }

    __syncthreads();
    float* sEpi = (float*)sAct;   // 128*33*4 = 16896 B <= 20800 B
#pragma unroll
    for (int mt = 0; mt < 2; mt++)
#pragma unroll
        for (int nt = 0; nt < 4; nt++) {
            int r = wid * 32 + mt * 16 + (lane >> 2);
            int c = nt * 8 + (lane & 3) * 2;
            sEpi[r * 33 + c]           = acc[mt][nt][0];
            sEpi[r * 33 + c + 1]       = acc[mt][nt][1];
            sEpi[(r + 8) * 33 + c]     = acc[mt][nt][2];
            sEpi[(r + 8) * 33 + c + 1] = acc[mt][nt][3];
        }
    __syncthreads();

    if (tid < 104) {
        int w = w0 + tid;
#pragma unroll
        for (int oc = 0; oc < 32; oc++) {
            long long idx = ((long long)(oc * DD + d) * HH + h) * WW + w;
            float val = sEpi[tid * 33 + oc] + sBias[oc] + xres[idx];
            out[idx] = fmaxf(val, 0.f);
        }
    }
}

// ---------- launcher ----------
extern "C" void kernel_launch(void* const* d_in, const int* in_sizes, int n_in,
                              void* d_out, int out_size) {
    const float* x  = (const float*)d_in[0];
    const float* g  = (const float*)d_in[1];
    const float* cw = (const float*)d_in[2];
    const float* g1 = (const float*)d_in[3];
    const float* b1 = (const float*)d_in[4];
    const float* m1 = (const float*)d_in[5];
    const float* v1 = (const float*)d_in[6];
    const float* g2 = (const float*)d_in[7];
    const float* b2 = (const float*)d_in[8];
    const float* m2 = (const float*)d_in[9];
    const float* v2 = (const float*)d_in[10];
    float* out = (float*)d_out;

    k_norm<<<(4 * HW + 255) / 256, 256>>>(g);
    k_wfrag<<<(2 * 27 * 512 + 255) / 256, 256>>>(cw, g1, b1, m1, v1, g2, b2, m2, v2);
    k_transpose<<<DD * HH, 256>>>(x);
    k_scan<<<dim3(544, 2), 32>>>();
    k_combine<<<(NELEM / 4 + 255) / 256, 256>>>();
    k_mma<<<dim3(HH, DD, 2), 128>>>(x, out);
}

// round 9
// speedup vs baseline: 2.6959x; 1.1525x over previous
#include <cuda_runtime.h>
#include <cuda_bf16.h>
#include <cstdint>
#include <cstring>

#define CC 32
#define DD 48
#define HH 64
#define WW 208
#define HW 13312            // HH*WW
#define NELEM (CC*DD*HH*WW) // 20447232
#define CEPS 1e-5f
#define NEGINF -3.402823e38f

typedef unsigned long long ull;

// ---------- scratch (device globals: allocation-free) ----------
__device__ float g_kn[4 * 5 * HW];        // normalized guidance
__device__ float g_xt[NELEM];             // x transposed [d][h][w][c]
__device__ float g_accA[NELEM];           // W fwd
__device__ float g_accB[NELEM];           // W bwd
__device__ float g_accC[NELEM];           // H fwd
__device__ float g_accD[NELEM];           // H bwd
__device__ __nv_bfloat16 g_bh[NELEM];     // activation hi split [d][h][w][c]
__device__ __nv_bfloat16 g_bl[NELEM];     // activation lo split
__device__ uint32_t g_wfrag[2 * 27 * 512]; // B fragments [sp][tap][kt][nt][lane][reg]
__device__ float g_bias2[32];
__device__ float g_s1v[32];
__device__ float g_b1v[32];

// ---------- helpers ----------
__device__ __forceinline__ uint32_t smem_u32(const void* p) {
    uint32_t a;
    asm("{ .reg .u64 t; cvta.to.shared.u64 t, %1; cvt.u32.u64 %0, t; }" : "=r"(a) : "l"(p));
    return a;
}
__device__ __forceinline__ void ldm4(uint32_t* r, uint32_t addr) {
    asm volatile("ldmatrix.sync.aligned.m8n8.x4.shared.b16 {%0,%1,%2,%3}, [%4];"
                 : "=r"(r[0]), "=r"(r[1]), "=r"(r[2]), "=r"(r[3]) : "r"(addr));
}
__device__ __forceinline__ void mma16816(float* c, const uint32_t* a, uint32_t b0, uint32_t b1) {
    asm volatile("mma.sync.aligned.m16n8k16.row.col.f32.bf16.bf16.f32 "
                 "{%0,%1,%2,%3}, {%4,%5,%6,%7}, {%8,%9}, {%0,%1,%2,%3};"
                 : "+f"(c[0]), "+f"(c[1]), "+f"(c[2]), "+f"(c[3])
                 : "r"(a[0]), "r"(a[1]), "r"(a[2]), "r"(a[3]), "r"(b0), "r"(b1));
}
__device__ __forceinline__ unsigned short bf16bits(__nv_bfloat16 v) {
    unsigned short s;
    memcpy(&s, &v, 2);
    return s;
}
__device__ __forceinline__ void cpasync16(uint32_t d, const void* s, bool valid) {
    int sz = valid ? 16 : 0;
    asm volatile("cp.async.cg.shared.global [%0], [%1], 16, %2;"
                 :: "r"(d), "l"(s), "r"(sz) : "memory");
}
__device__ __forceinline__ void cpasync_commit_wait() {
    asm volatile("cp.async.commit_group;" ::: "memory");
    asm volatile("cp.async.wait_group 0;" ::: "memory");
}

// ---------- 1) guidance L1 normalization ----------
__global__ void k_norm(const float* __restrict__ g) {
    int i = blockIdx.x * blockDim.x + threadIdx.x;
    if (i >= 4 * HW) return;
    int dir = i / HW;
    int hw  = i % HW;
    float v[5];
    float s = 0.f;
#pragma unroll
    for (int j = 0; j < 5; j++) {
        v[j] = g[(5 * dir + j) * HW + hw];
        s += fabsf(v[j]);
    }
    float inv = 1.f / fmaxf(s, 1e-12f);
#pragma unroll
    for (int j = 0; j < 5; j++)
        g_kn[(dir * 5 + j) * HW + hw] = v[j] * inv;
}

// ---------- 2) transpose NCDHW -> [d][h][w][c] ----------
__global__ void k_transpose(const float* __restrict__ x) {
    __shared__ float t[32][209];
    int d = blockIdx.x / HH;
    int h = blockIdx.x % HH;
    for (int i = threadIdx.x; i < 32 * WW; i += blockDim.x) {
        int c = i / WW, w = i % WW;
        t[c][w] = x[((c * DD + d) * HH + h) * WW + w];
    }
    __syncthreads();
    float* dst = g_xt + (d * HH + h) * WW * 32;
    for (int i = threadIdx.x; i < WW * 32; i += blockDim.x) {
        dst[i] = t[i & 31][i >> 5];
    }
}

// ---------- 3) prep: BN params + bf16-split B fragments in mma frag order ----------
__global__ void k_wfrag(const float* __restrict__ cw,
                        const float* __restrict__ g1, const float* __restrict__ b1,
                        const float* __restrict__ m1, const float* __restrict__ v1,
                        const float* __restrict__ g2, const float* __restrict__ b2,
                        const float* __restrict__ m2, const float* __restrict__ v2) {
    int i = blockIdx.x * blockDim.x + threadIdx.x;
    if (i < 2 * 27 * 512) {
        int reg  = i & 1;
        int lane = (i >> 1) & 31;
        int nt   = (i >> 6) & 3;
        int kt   = (i >> 8) & 1;
        int rest = i >> 9;
        int tap  = rest % 27;
        int sp   = rest / 27;
        int oc   = nt * 8 + (lane >> 2);
        int icb  = kt * 16 + (lane & 3) * 2 + reg * 8;
        float s2 = g2[oc] * rsqrtf(v2[oc] + CEPS);
        uint32_t pack = 0;
#pragma unroll
        for (int e = 0; e < 2; e++) {
            int ic = icb + e;
            float wv = cw[(oc * 32 + ic) * 27 + tap] * s2;
            __nv_bfloat16 wh = __float2bfloat16(wv);
            __nv_bfloat16 val = sp ? __float2bfloat16(wv - __bfloat162float(wh)) : wh;
            pack |= (uint32_t)bf16bits(val) << (16 * e);
        }
        g_wfrag[i] = pack;
    }
    if (i < 32) {
        float s2 = g2[i] * rsqrtf(v2[i] + CEPS);
        g_bias2[i] = b2[i] - m2[i] * s2;
        float s1 = g1[i] * rsqrtf(v1[i] + CEPS);
        g_s1v[i] = s1;
        g_b1v[i] = b1[i] - m1[i] * s1;
    }
}

// ---------- 4) fused 4-direction scan (R6 config: 2176 warps, 8ch/lane) ----------
__global__ void __launch_bounds__(32) k_scan() {
    int lane = threadIdx.x;
    int ds = lane >> 3;
    int cl = lane & 7;
    int bx = blockIdx.x;

    int nsteps, pitch, p0;
    const float* kb; float* ob; int kpitch;
    int cg;
    int planeIdx0;
    if (bx < 512) {
        int h = bx & 63;
        int dir = (bx >> 6) & 1;
        cg = bx >> 7;
        nsteps = WW;
        kb = g_kn + dir * 5 * HW + h * WW;
        ob = dir ? g_accB : g_accA;
        int ps = dir ? -1 : 1;
        p0 = dir ? (WW - 1) : 0;
        pitch = ps;
        kpitch = ps;
        planeIdx0 = h * WW + p0;
    } else {
        int i = bx - 512;
        int w = i % 208;
        int r = i / 208;
        int dir = r & 1;
        cg = r >> 1;
        nsteps = HH;
        kb = g_kn + (2 + dir) * 5 * HW + w;
        ob = dir ? g_accD : g_accC;
        int hs = dir ? -1 : 1;
        int h0 = dir ? (HH - 1) : 0;
        pitch = hs * WW;
        kpitch = hs * WW;
        planeIdx0 = h0 * WW + w;
        p0 = h0 * WW;
    }
    int c = cg * 8 + cl;
    int d0 = ds * 12;

    const float* xp = g_xt + ((long long)d0 * HW + planeIdx0) * 32 + c;
    float* op = ob + ((long long)d0 * HW + planeIdx0) * 32 + c;
    const long long DSTR = (long long)HW * 32;
    const long long PSTR = (long long)pitch * 32;
    const float* kp;
    if (bx < 512) kp = kb + ((pitch > 0) ? 0 : (WW - 1));
    else kp = kb + p0;

    float A[12], xv[12], wv[5];
    float lmx = NEGINF;
#pragma unroll
    for (int j = 0; j < 12; j++) {
        xv[j] = xp[j * DSTR];
        A[j] = xv[j];
        lmx = fmaxf(lmx, A[j]);
    }
#pragma unroll
    for (int j = 0; j < 5; j++) wv[j] = kp[j * HW];
    float gmx = fmaxf(lmx, __shfl_xor_sync(0xffffffffu, lmx, 8));
    gmx = fmaxf(gmx, __shfl_xor_sync(0xffffffffu, gmx, 16));

    for (int s = 0; s < nsteps; s++) {
        bool last = (s == nsteps - 1);
        const float* xpn = last ? xp : (xp + PSTR);
        const float* kpn = last ? kp : (kp + kpitch);
        float xn[12], wn[5];
#pragma unroll
        for (int j = 0; j < 12; j++) xn[j] = xpn[j * DSTR];
#pragma unroll
        for (int j = 0; j < 5; j++) wn[j] = kpn[j * HW];

        float fromUp = __shfl_up_sync(0xffffffffu, A[11], 8);
        float fromDn = __shfl_down_sync(0xffffffffu, A[0], 8);
        float up0   = (ds == 0) ? A[0]  : fromUp;
        float dnTop = (ds == 3) ? A[11] : fromDn;
        float w0 = wv[0], w1 = wv[1], w2 = wv[2], w3 = wv[3], w4 = wv[4];
        float prevOld = A[0];
#pragma unroll
        for (int j = 0; j < 12; j++) {
            float old = A[j];
            float up = (j == 0) ? up0 : prevOld;
            float dn = (j == 11) ? dnTop : A[j + 1];
            float nv = w0 * xv[j] + w1 * old + w2 * up + w3 * dn + w4 * gmx;
            op[j * DSTR] = nv;
            A[j] = nv;
            prevOld = old;
        }
        float t0 = fmaxf(A[0], A[1]),  t1 = fmaxf(A[2], A[3]);
        float t2 = fmaxf(A[4], A[5]),  t3 = fmaxf(A[6], A[7]);
        float t4 = fmaxf(A[8], A[9]),  t5 = fmaxf(A[10], A[11]);
        float u0 = fmaxf(t0, t1), u1 = fmaxf(t2, t3), u2 = fmaxf(t4, t5);
        float lm = fmaxf(u0, fmaxf(u1, u2));
        lm = fmaxf(lm, __shfl_xor_sync(0xffffffffu, lm, 8));
        gmx = fmaxf(lm, __shfl_xor_sync(0xffffffffu, lm, 16));

#pragma unroll
        for (int j = 0; j < 12; j++) xv[j] = xn[j];
#pragma unroll
        for (int j = 0; j < 5; j++) wv[j] = wn[j];
        xp = xpn;
        kp = kpn;
        op += PSTR;
    }
}

// ---------- 5) combine: relu(bn1(max4)) -> bf16 hi/lo splits, [d][h][w][c] ----------
__global__ void __launch_bounds__(256) k_combine() {
    __shared__ float s1s[32], b1s[32];
    int tid = threadIdx.x;
    if (tid < 32) { s1s[tid] = g_s1v[tid]; b1s[tid] = g_b1v[tid]; }
    __syncthreads();
    int i = blockIdx.x * 256 + tid;
    if (i >= NELEM / 4) return;
    float4 a = ((const float4*)g_accA)[i];
    float4 b = ((const float4*)g_accB)[i];
    float4 cc = ((const float4*)g_accC)[i];
    float4 dd = ((const float4*)g_accD)[i];
    int c0 = (i * 4) & 31;
    float v[4];
    v[0] = fmaxf(fmaxf(fmaxf(a.x, b.x), fmaxf(cc.x, dd.x)) * s1s[c0 + 0] + b1s[c0 + 0], 0.f);
    v[1] = fmaxf(fmaxf(fmaxf(a.y, b.y), fmaxf(cc.y, dd.y)) * s1s[c0 + 1] + b1s[c0 + 1], 0.f);
    v[2] = fmaxf(fmaxf(fmaxf(a.z, b.z), fmaxf(cc.z, dd.z)) * s1s[c0 + 2] + b1s[c0 + 2], 0.f);
    v[3] = fmaxf(fmaxf(fmaxf(a.w, b.w), fmaxf(cc.w, dd.w)) * s1s[c0 + 3] + b1s[c0 + 3], 0.f);
    uint32_t hp[2], lp[2];
#pragma unroll
    for (int j = 0; j < 2; j++) {
        __nv_bfloat16 h0 = __float2bfloat16(v[2 * j]);
        __nv_bfloat16 h1 = __float2bfloat16(v[2 * j + 1]);
        __nv_bfloat16 l0 = __float2bfloat16(v[2 * j] - __bfloat162float(h0));
        __nv_bfloat16 l1 = __float2bfloat16(v[2 * j + 1] - __bfloat162float(h1));
        hp[j] = (uint32_t)bf16bits(h0) | ((uint32_t)bf16bits(h1) << 16);
        lp[j] = (uint32_t)bf16bits(l0) | ((uint32_t)bf16bits(l1) << 16);
    }
    ((uint2*)g_bh)[i] = make_uint2(hp[0], hp[1]);
    ((uint2*)g_bl)[i] = make_uint2(lp[0], lp[1]);
}

// ---------- 6) conv via warp HMMA: 27 shifted GEMMs, 2-term split ----------
// CTA = M=128 w-rows (valid 104) x N=32 oc; 4 warps each m32 x n32.
// sAct rows padded to 40 bf16 (80B) -> conflict-free ldmatrix.
// B fragments read directly from global via __ldg (110KB set, L1-resident).
#define AROW 40
#define ASP_OFF (130 * AROW)            // bf16 elems per split
__global__ void __launch_bounds__(128) k_mma(const float* __restrict__ xres,
                                             float* __restrict__ out) {
    __shared__ alignas(16) __nv_bfloat16 sAct[2 * ASP_OFF];   // 20800 B
    __shared__ float sBias[32];

    int tid = threadIdx.x;
    int wid = tid >> 5;
    int lane = tid & 31;
    int h = blockIdx.x;
    int d = blockIdx.y;
    int w0 = blockIdx.z * 104;

    if (tid < 32) sBias[tid] = g_bias2[tid];

    uint32_t sact_u = smem_u32(sAct);
    uint32_t lm_lane = (uint32_t)((lane & 15) * (AROW * 2) + (lane >> 4) * 16);

    float acc[2][4][4];
#pragma unroll
    for (int mt = 0; mt < 2; mt++)
#pragma unroll
        for (int nt = 0; nt < 4; nt++)
#pragma unroll
            for (int r = 0; r < 4; r++) acc[mt][nt][r] = 0.f;

#pragma unroll
    for (int kd = 0; kd < 3; kd++) {
        int din = d + kd - 1;
        if ((unsigned)din >= DD) continue;
#pragma unroll
        for (int kh = 0; kh < 3; kh++) {
            int hin = h + kh - 1;
            if ((unsigned)hin >= HH) continue;

            __syncthreads();    // previous phase's reads complete
            // stage activations via cp.async: rows w0-1..w0+128 (130) x 32 bf16, hi+lo
            {
                long long rowb = (long long)(din * HH + hin) * WW;
                for (int c = tid; c < 1040; c += 128) {
                    int sp  = c / 520;
                    int rem = c - sp * 520;
                    int r = rem >> 2, q = rem & 3;
                    int w = w0 - 1 + r;
                    bool valid = (unsigned)w < WW;
                    int wc = valid ? w : 0;
                    const __nv_bfloat16* gs = (sp ? g_bl : g_bh) + (rowb + wc) * 32 + q * 8;
                    cpasync16(sact_u + (uint32_t)((sp * ASP_OFF + r * AROW) * 2 + q * 16),
                              gs, valid);
                }
            }
            cpasync_commit_wait();
            __syncthreads();

            int tap3 = kd * 9 + kh * 3;
#pragma unroll
            for (int kw = 0; kw < 3; kw++) {
                uint32_t Afr[2][2][2][4];       // [asp][mt][kt][4]
#pragma unroll
                for (int asp = 0; asp < 2; asp++)
#pragma unroll
                    for (int mt = 0; mt < 2; mt++)
#pragma unroll
                        for (int kt = 0; kt < 2; kt++) {
                            uint32_t addr = sact_u + (uint32_t)(asp * ASP_OFF * 2) + lm_lane
                                          + (uint32_t)((wid * 32 + mt * 16 + kw) * (AROW * 2)
                                                       + kt * 32);
                            ldm4(Afr[asp][mt][kt], addr);
                        }
                uint2 Bfr[2][2][4];             // [bsp][kt][nt]
#pragma unroll
                for (int bsp = 0; bsp < 2; bsp++) {
                    const uint2* wb = (const uint2*)(g_wfrag + (bsp * 27 + tap3 + kw) * 512);
#pragma unroll
                    for (int kt = 0; kt < 2; kt++)
#pragma unroll
                        for (int nt = 0; nt < 4; nt++)
                            Bfr[bsp][kt][nt] = __ldg(&wb[(kt * 4 + nt) * 32 + lane]);
                }
#pragma unroll
                for (int cb = 0; cb < 3; cb++) {        // (ah,bh), (ah,bl), (al,bh)
                    int asp = (cb == 2) ? 1 : 0;
                    int bsp = (cb == 1) ? 1 : 0;
#pragma unroll
                    for (int mt = 0; mt < 2; mt++)
#pragma unroll
                        for (int nt = 0; nt < 4; nt++)
#pragma unroll
                            for (int kt = 0; kt < 2; kt++)
                                mma16816(acc[mt][nt], Afr[asp][mt][kt],
                                         Bfr[bsp][kt][nt].x, Bfr[bsp][kt][nt].y);
                }
            }
        }
    }

    __syncthreads();
    float* sEpi = (float*)sAct;   // 128*33*4 = 16896 B <= 20800 B
#pragma unroll
    for (int mt = 0; mt < 2; mt++)
#pragma unroll
        for (int nt = 0; nt < 4; nt++) {
            int r = wid * 32 + mt * 16 + (lane >> 2);
            int c = nt * 8 + (lane & 3) * 2;
            sEpi[r * 33 + c]           = acc[mt][nt][0];
            sEpi[r * 33 + c + 1]       = acc[mt][nt][1];
            sEpi[(r + 8) * 33 + c]     = acc[mt][nt][2];
            sEpi[(r + 8) * 33 + c + 1] = acc[mt][nt][3];
        }
    __syncthreads();

    if (tid < 104) {
        int w = w0 + tid;
#pragma unroll
        for (int oc = 0; oc < 32; oc++) {
            long long idx = ((long long)(oc * DD + d) * HH + h) * WW + w;
            float val = sEpi[tid * 33 + oc] + sBias[oc] + xres[idx];
            out[idx] = fmaxf(val, 0.f);
        }
    }
}

// ---------- launcher ----------
extern "C" void kernel_launch(void* const* d_in, const int* in_sizes, int n_in,
                              void* d_out, int out_size) {
    const float* x  = (const float*)d_in[0];
    const float* g  = (const float*)d_in[1];
    const float* cw = (const float*)d_in[2];
    const float* g1 = (const float*)d_in[3];
    const float* b1 = (const float*)d_in[4];
    const float* m1 = (const float*)d_in[5];
    const float* v1 = (const float*)d_in[6];
    const float* g2 = (const float*)d_in[7];
    const float* b2 = (const float*)d_in[8];
    const float* m2 = (const float*)d_in[9];
    const float* v2 = (const float*)d_in[10];
    float* out = (float*)d_out;

    k_norm<<<(4 * HW + 255) / 256, 256>>>(g);
    k_wfrag<<<(2 * 27 * 512 + 255) / 256, 256>>>(cw, g1, b1, m1, v1, g2, b2, m2, v2);
    k_transpose<<<DD * HH, 256>>>(x);
    k_scan<<<2176, 32>>>();
    k_combine<<<(NELEM / 4 + 255) / 256, 256>>>();
    k_mma<<<dim3(HH, DD, 2), 128>>>(x, out);
}